// round 6
// baseline (speedup 1.0000x reference)
#include <cuda_runtime.h>
#include <math.h>
#include <float.h>

// ---------------------------------------------------------------------------
// MultiLatentSpaceSimilarity — fp32 f32x2; broadcast operand duplicated in
// smem ({v,v} pairs, warp-uniform LDS -> no pack MOVs), 2 CTAs/SM.
// B=16, C=256, S=1024, 3 groups x 8 splits, L=64, HEADS=8, DH=64, INNER=512
// ---------------------------------------------------------------------------

constexpr int B_ = 16, C_ = 256, S_ = 1024;
constexpr int SPLITS_ = 8, L_ = 64, HEADS_ = 8, DH_ = 64, INNER_ = 512;
constexpr float SCALE_ = 0.125f;

// Static device scratch
__device__ float g_K[(size_t)B_ * INNER_ * S_];   // [b][h*64+d][s]
__device__ float g_V[(size_t)B_ * INNER_ * S_];   // [b][h*64+d][s]
__device__ float g_Q[SPLITS_ * L_ * INNER_];      // [p][l][n]
__device__ float g_E[(size_t)B_ * HEADS_ * SPLITS_ * L_ * S_]; // [bhp][l][s]
__device__ float g_Zp[B_ * HEADS_ * SPLITS_ * 4 * L_];         // partial Z
__device__ float g_invZ[B_ * HEADS_ * SPLITS_ * L_];           // 1/Z
__device__ float g_outp[(size_t)4 * 128 * 2 * 64 * 256];       // [sz][bh][rowG][d][row]
__device__ float g_heatp[(size_t)B_ * SPLITS_ * HEADS_ * S_];  // [(b*8+p)*8+h][s]
__device__ float g_distp[B_ * HEADS_ * SPLITS_];

typedef unsigned long long ull;

__device__ __forceinline__ void ffma2(ull& d, ull a, ull b)
{
    asm("fma.rn.f32x2 %0, %1, %2, %0;" : "+l"(d) : "l"(a), "l"(b));
}
__device__ __forceinline__ float2 unpk(ull v)
{
    float2 r;
    asm("mov.b64 {%0, %1}, %2;" : "=f"(r.x), "=f"(r.y) : "l"(v));
    return r;
}
// load 8 duplicated {v,v} pairs (16 floats, warp-uniform -> broadcast LDS)
__device__ __forceinline__ void ld_dup8(const float* p, ull* w)
{
    ulonglong2 a = *(const ulonglong2*)p;
    ulonglong2 b = *(const ulonglong2*)(p + 4);
    ulonglong2 c = *(const ulonglong2*)(p + 8);
    ulonglong2 d = *(const ulonglong2*)(p + 12);
    w[0] = a.x; w[1] = a.y; w[2] = b.x; w[3] = b.y;
    w[4] = c.x; w[5] = c.y; w[6] = d.x; w[7] = d.y;
}
__device__ __forceinline__ void st_dup4(float* p, float4 v)
{
    *(float2*)(p + 0) = make_float2(v.x, v.x);
    *(float2*)(p + 2) = make_float2(v.y, v.y);
    *(float2*)(p + 4) = make_float2(v.z, v.z);
    *(float2*)(p + 6) = make_float2(v.w, v.w);
}

// ---------------------------------------------------------------------------
// K/V projection: out[b][n][m] = sum_c A[b][c][m] * W[c][n]
// Tile 256(m) x 64(n); tx -> m (8/lane), wy -> n (8/warp, dup broadcast).
// ---------------------------------------------------------------------------
template <int DST>
__global__ __launch_bounds__(256, 2) void projKV_kernel(
    const float* __restrict__ A, const float* __restrict__ W)
{
    extern __shared__ float sm[];
    float* As = sm;                 // [32][256]
    float* Wd = sm + 32 * 256;      // [32][136] dup pairs

    float* outp = (DST == 0) ? g_K : g_V;
    int tid = threadIdx.x;
    int tx = tid & 31, wy = tid >> 5;
    int m0 = blockIdx.x * 256, n0 = blockIdx.y * 64;
    int batch = blockIdx.z;
    const float* Ab = A + (size_t)batch * C_ * S_;

    ull acc[8][4] = {};                          // [n][m-pair]
    for (int c0 = 0; c0 < C_; c0 += 32) {
        __syncthreads();
        #pragma unroll
        for (int it = 0; it < 8; it++) {
            int idx = tid + it * 256;
            int c = idx >> 6, mq = idx & 63;
            *(float4*)&As[c * 256 + mq * 4] =
                *(const float4*)&Ab[(size_t)(c0 + c) * S_ + m0 + mq * 4];
        }
        #pragma unroll
        for (int it = 0; it < 2; it++) {
            int idx = tid + it * 256;
            int c = idx >> 4, nq = idx & 15;
            float4 w = *(const float4*)&W[(size_t)(c0 + c) * INNER_ + n0 + nq * 4];
            st_dup4(&Wd[c * 136 + nq * 8], w);
        }
        __syncthreads();
        #pragma unroll 8
        for (int c = 0; c < 32; c++) {
            const float* ar = &As[c * 256 + tx * 8];
            ulonglong2 a01 = *(const ulonglong2*)ar;
            ulonglong2 a23 = *(const ulonglong2*)(ar + 4);
            ull ap[4] = {a01.x, a01.y, a23.x, a23.y};
            ull wp[8];
            ld_dup8(&Wd[c * 136 + wy * 16], wp);
            #pragma unroll
            for (int ni = 0; ni < 8; ni++)
                #pragma unroll
                for (int mj = 0; mj < 4; mj++)
                    ffma2(acc[ni][mj], wp[ni], ap[mj]);
        }
    }

    #pragma unroll
    for (int ni = 0; ni < 8; ni++) {
        int n = n0 + wy * 8 + ni;
        float2 f0 = unpk(acc[ni][0]), f1 = unpk(acc[ni][1]);
        float2 f2 = unpk(acc[ni][2]), f3 = unpk(acc[ni][3]);
        float* orow = &outp[((size_t)batch * INNER_ + n) * S_ + m0 + tx * 8];
        *(float4*)&orow[0] = make_float4(f0.x, f0.y, f1.x, f1.y);
        *(float4*)&orow[4] = make_float4(f2.x, f2.y, f3.x, f3.y);
    }
}

// ---------------------------------------------------------------------------
// Q projection (small). out g_Q[p][l][n]
// ---------------------------------------------------------------------------
__global__ void projQ_kernel(const float* __restrict__ A,
                             const float* __restrict__ W)
{
    __shared__ __align__(16) float As[32][68];   // [c][l]
    __shared__ __align__(16) float Wd[32][132];  // [c][2n] dup
    int tid = threadIdx.x;
    int txq = tid & 15, tyq = tid >> 4;
    int n0 = blockIdx.y * 64;
    int p = blockIdx.z;
    const float* Ab = A + (size_t)p * C_ * L_;

    ull acc[4][2] = {};
    for (int c0 = 0; c0 < C_; c0 += 32) {
        __syncthreads();
        for (int idx = tid; idx < 512; idx += 256) {
            int c = idx >> 4, q = idx & 15;
            *(float4*)&As[c][q * 4] =
                *(const float4*)&Ab[(size_t)(c0 + c) * L_ + q * 4];
            float4 w = *(const float4*)&W[(size_t)(c0 + c) * INNER_ + n0 + q * 4];
            Wd[c][q * 8 + 0] = w.x; Wd[c][q * 8 + 1] = w.x;
            Wd[c][q * 8 + 2] = w.y; Wd[c][q * 8 + 3] = w.y;
            Wd[c][q * 8 + 4] = w.z; Wd[c][q * 8 + 5] = w.z;
            Wd[c][q * 8 + 6] = w.w; Wd[c][q * 8 + 7] = w.w;
        }
        __syncthreads();
        #pragma unroll
        for (int cc = 0; cc < 32; cc++) {
            ulonglong2 am  = *(ulonglong2*)&As[cc][txq * 4];
            ulonglong2 w01 = *(ulonglong2*)&Wd[cc][tyq * 8];
            ulonglong2 w23 = *(ulonglong2*)&Wd[cc][tyq * 8 + 4];
            ffma2(acc[0][0], w01.x, am.x); ffma2(acc[0][1], w01.x, am.y);
            ffma2(acc[1][0], w01.y, am.x); ffma2(acc[1][1], w01.y, am.y);
            ffma2(acc[2][0], w23.x, am.x); ffma2(acc[2][1], w23.x, am.y);
            ffma2(acc[3][0], w23.y, am.x); ffma2(acc[3][1], w23.y, am.y);
        }
    }
    #pragma unroll
    for (int i4 = 0; i4 < 4; i4++) {
        int n = n0 + tyq * 4 + i4;
        float2 a = unpk(acc[i4][0]), b2 = unpk(acc[i4][1]);
        int l = txq * 4;
        g_Q[((size_t)p * L_ + l + 0) * INNER_ + n] = a.x;
        g_Q[((size_t)p * L_ + l + 1) * INNER_ + n] = a.y;
        g_Q[((size_t)p * L_ + l + 2) * INNER_ + n] = b2.x;
        g_Q[((size_t)p * L_ + l + 3) * INNER_ + n] = b2.y;
    }
}

// ---------------------------------------------------------------------------
// Scores: E[l,s]=exp(SCALE*q.k), Zp partial sums. Grid (4 sq, 1024 bhp).
// tx -> s (8/lane), wy -> l (8/warp, dup broadcast). d tiled 2x32.
// ---------------------------------------------------------------------------
__global__ __launch_bounds__(256, 2) void scores_kernel()
{
    extern __shared__ float sm[];
    float* Kt = sm;                 // [32][256]
    float* Qd = sm + 32 * 256;      // [32][136]  dup pairs Qd[d][2l]

    int sq = blockIdx.x;
    int bhp = blockIdx.y;
    int p = bhp & 7, h = (bhp >> 3) & 7, b = bhp >> 6;
    int s0 = sq * 256;
    int tid = threadIdx.x;
    int tx = tid & 31, wy = tid >> 5;

    const float* kbase = g_K + ((size_t)(b * HEADS_ + h) * DH_) * S_ + s0;
    const float* qbase = g_Q + (size_t)p * L_ * INNER_ + h * DH_;

    ull acc[8][4] = {};                          // [l][s-pair]
    for (int d0 = 0; d0 < 64; d0 += 32) {
        __syncthreads();
        #pragma unroll
        for (int it = 0; it < 8; it++) {
            int idx = tid + it * 256;
            int d = idx >> 6, sqq = idx & 63;
            *(float4*)&Kt[d * 256 + sqq * 4] =
                *(const float4*)&kbase[(size_t)(d0 + d) * S_ + sqq * 4];
        }
        #pragma unroll
        for (int it = 0; it < 2; it++) {
            int idx = tid + it * 256;
            int dq = idx & 7, l = idx >> 3;
            float4 q = *(const float4*)&qbase[(size_t)l * INNER_ + d0 + dq * 4];
            Qd[(dq * 4 + 0) * 136 + 2 * l] = q.x; Qd[(dq * 4 + 0) * 136 + 2 * l + 1] = q.x;
            Qd[(dq * 4 + 1) * 136 + 2 * l] = q.y; Qd[(dq * 4 + 1) * 136 + 2 * l + 1] = q.y;
            Qd[(dq * 4 + 2) * 136 + 2 * l] = q.z; Qd[(dq * 4 + 2) * 136 + 2 * l + 1] = q.z;
            Qd[(dq * 4 + 3) * 136 + 2 * l] = q.w; Qd[(dq * 4 + 3) * 136 + 2 * l + 1] = q.w;
        }
        __syncthreads();
        #pragma unroll 8
        for (int d = 0; d < 32; d++) {
            const float* kr = &Kt[d * 256 + tx * 8];
            ulonglong2 k01 = *(const ulonglong2*)kr;
            ulonglong2 k23 = *(const ulonglong2*)(kr + 4);
            ull kp[4] = {k01.x, k01.y, k23.x, k23.y};
            ull qp[8];
            ld_dup8(&Qd[d * 136 + wy * 16], qp);
            #pragma unroll
            for (int li = 0; li < 8; li++)
                #pragma unroll
                for (int sj = 0; sj < 4; sj++)
                    ffma2(acc[li][sj], qp[li], kp[sj]);
        }
    }

    float* erow = g_E + (size_t)bhp * L_ * S_ + s0;
    #pragma unroll
    for (int li = 0; li < 8; li++) {
        int l = wy * 8 + li;
        float2 a0 = unpk(acc[li][0]), a1 = unpk(acc[li][1]);
        float2 a2 = unpk(acc[li][2]), a3 = unpk(acc[li][3]);
        float e0 = __expf(a0.x * SCALE_), e1 = __expf(a0.y * SCALE_);
        float e2 = __expf(a1.x * SCALE_), e3 = __expf(a1.y * SCALE_);
        float e4 = __expf(a2.x * SCALE_), e5 = __expf(a2.y * SCALE_);
        float e6 = __expf(a3.x * SCALE_), e7 = __expf(a3.y * SCALE_);
        float* ep = &erow[(size_t)l * S_ + tx * 8];
        *(float4*)&ep[0] = make_float4(e0, e1, e2, e3);
        *(float4*)&ep[4] = make_float4(e4, e5, e6, e7);
        float z = ((e0 + e1) + (e2 + e3)) + ((e4 + e5) + (e6 + e7));
        #pragma unroll
        for (int off = 16; off; off >>= 1)
            z += __shfl_xor_sync(0xffffffffu, z, off);
        if (tx == 0) g_Zp[(bhp * 4 + sq) * 64 + l] = z;
    }
}

// ---------------------------------------------------------------------------
// invZ[bhp*64+l] = 1 / sum_j Zp[(bhp*4+j)*64+l]
// ---------------------------------------------------------------------------
__global__ void invz_kernel()
{
    int i = blockIdx.x * 256 + threadIdx.x;
    int bhp = i >> 6, l = i & 63;
    float z = 0.f;
    #pragma unroll
    for (int j = 0; j < 4; j++) z += g_Zp[(bhp * 4 + j) * 64 + l];
    g_invZ[i] = 1.0f / z;
}

// ---------------------------------------------------------------------------
// Out slices: rows = 256 (4 p's x 64 l, shared V), d = 64, s-slice = 256.
// Grid (2 rowG, 4 sz, 128 bh). tx -> rows (8/lane), wy -> d (8/warp, dup V).
// ---------------------------------------------------------------------------
__global__ __launch_bounds__(256, 2) void out_slice_kernel()
{
    extern __shared__ float sm[];
    float* Es    = sm;                       // [32][260]  Es[s][row]
    float* Vd    = sm + 32 * 260;            // [32][136]  dup Vd[s][2d]
    float* invZs = sm + 32 * 260 + 32 * 136; // [256] (4p x 64l)

    int rowG = blockIdx.x;
    int sz   = blockIdx.y;
    int bh   = blockIdx.z;
    int b = bh >> 3, h = bh & 7;
    int tid = threadIdx.x;
    int tx = tid & 31, wy = tid >> 5;

    {
        int p_loc = tid >> 6, l = tid & 63;
        int bhp = bh * 8 + rowG * 4 + p_loc;
        invZs[tid] = g_invZ[bhp * 64 + l];
    }

    const float* vbase = g_V + ((size_t)(b * HEADS_ + h) * DH_) * S_;
    size_t ebase = ((size_t)(bh * 8 + rowG * 4)) * L_ * S_;

    ull acc[8][4] = {};                      // [d][row-pair]
    for (int c = 0; c < 8; c++) {
        int s0 = sz * 256 + c * 32;
        __syncthreads();
        #pragma unroll
        for (int it = 0; it < 8; it++) {
            int idx = tid + it * 256;
            int sq4 = idx & 7, r = idx >> 3;
            float4 e = *(const float4*)&g_E[ebase + (size_t)r * S_ + s0 + sq4 * 4];
            Es[(sq4 * 4 + 0) * 260 + r] = e.x;
            Es[(sq4 * 4 + 1) * 260 + r] = e.y;
            Es[(sq4 * 4 + 2) * 260 + r] = e.z;
            Es[(sq4 * 4 + 3) * 260 + r] = e.w;
        }
        #pragma unroll
        for (int it = 0; it < 2; it++) {
            int idx = tid + it * 256;
            int sq4 = idx & 7, d = idx >> 3;
            float4 v = *(const float4*)&vbase[(size_t)d * S_ + s0 + sq4 * 4];
            Vd[(sq4 * 4 + 0) * 136 + 2 * d] = v.x; Vd[(sq4 * 4 + 0) * 136 + 2 * d + 1] = v.x;
            Vd[(sq4 * 4 + 1) * 136 + 2 * d] = v.y; Vd[(sq4 * 4 + 1) * 136 + 2 * d + 1] = v.y;
            Vd[(sq4 * 4 + 2) * 136 + 2 * d] = v.z; Vd[(sq4 * 4 + 2) * 136 + 2 * d + 1] = v.z;
            Vd[(sq4 * 4 + 3) * 136 + 2 * d] = v.w; Vd[(sq4 * 4 + 3) * 136 + 2 * d + 1] = v.w;
        }
        __syncthreads();

        #pragma unroll 8
        for (int s = 0; s < 32; s++) {
            const float* er = &Es[s * 260 + tx * 8];
            ulonglong2 e01 = *(const ulonglong2*)er;
            ulonglong2 e23 = *(const ulonglong2*)(er + 4);
            ull ep[4] = {e01.x, e01.y, e23.x, e23.y};
            ull vp[8];
            ld_dup8(&Vd[s * 136 + wy * 16], vp);
            #pragma unroll
            for (int di = 0; di < 8; di++)
                #pragma unroll
                for (int rj = 0; rj < 4; rj++)
                    ffma2(acc[di][rj], vp[di], ep[rj]);
        }

        if (tid < 128) {
            int s_loc = tid & 31, p_loc = tid >> 5;
            float hacc = 0.f;
            #pragma unroll 16
            for (int l = 0; l < 64; l++)
                hacc += Es[s_loc * 260 + p_loc * 64 + l] * invZs[p_loc * 64 + l];
            int p = rowG * 4 + p_loc;
            g_heatp[((size_t)(b * SPLITS_ + p) * HEADS_ + h) * S_ + s0 + s_loc] = hacc;
        }
    }

    // transpose acc -> buf[d][row64] per row-quarter, write coalesced
    float* buf = Es;  // reuse ([64][68] = 4352 floats <= Es size)
    float* outBase = g_outp +
        (((size_t)(sz * 128 + bh) * 2 + rowG) * 64) * 256;
    for (int q = 0; q < 4; q++) {
        __syncthreads();
        if ((tx >> 3) == q) {
            int rl0 = (tx & 7) * 8;
            #pragma unroll
            for (int di = 0; di < 8; di++) {
                int d = wy * 8 + di;
                #pragma unroll
                for (int rj = 0; rj < 4; rj++) {
                    float2 f = unpk(acc[di][rj]);
                    *(float2*)&buf[d * 68 + rl0 + 2 * rj] = f;
                }
            }
        }
        __syncthreads();
        #pragma unroll
        for (int it = 0; it < 4; it++) {
            int idx = tid + it * 256;
            int d = idx >> 4, r4 = idx & 15;
            float4 v = *(float4*)&buf[d * 68 + r4 * 4];
            *(float4*)&outBase[(size_t)d * 256 + q * 64 + r4 * 4] = v;
        }
    }
}

// ---------------------------------------------------------------------------
// Finish: per bhp, sum 4 slice partials, normalize, dist = sum (q-out)^2.
// ---------------------------------------------------------------------------
__global__ void finish_kernel()
{
    int bhp = blockIdx.x;
    int p = bhp & 7, h = (bhp >> 3) & 7, b = bhp >> 6;
    int bh = b * 8 + h;
    int rowG = p >> 2, p_loc = p & 3;
    int tid = threadIdx.x;

    const float* qb = g_Q + (size_t)p * L_ * INNER_ + h * DH_;
    float ssum = 0.f;
    #pragma unroll
    for (int it = 0; it < 16; it++) {
        int idx = tid + it * 256;
        int d = idx >> 6, l = idx & 63;
        float v = 0.f;
        #pragma unroll
        for (int sz = 0; sz < 4; sz++)
            v += g_outp[(((size_t)(sz * 128 + bh) * 2 + rowG) * 64 + d) * 256 +
                        p_loc * 64 + l];
        float o = v * g_invZ[bhp * 64 + l];
        float diff = qb[(size_t)l * INNER_ + d] - o;
        ssum += diff * diff;
    }
    __shared__ float red[256];
    red[tid] = ssum;
    __syncthreads();
    for (int off = 128; off > 0; off >>= 1) {
        if (tid < off) red[tid] += red[tid + off];
        __syncthreads();
    }
    if (tid == 0) g_distp[bhp] = red[0];
}

// ---------------------------------------------------------------------------
__global__ void reduce_dist_kernel(float* __restrict__ out, int col0)
{
    int t = threadIdx.x;
    if (t < B_ * SPLITS_) {
        int p = t & 7, b = t >> 3;
        float s = 0.f;
        #pragma unroll
        for (int h = 0; h < HEADS_; h++) s += g_distp[b * 64 + h * 8 + p];
        out[b * 24 + col0 + p] = s * (1.0f / (L_ * INNER_));
    }
}

__global__ void argmax_kernel(float* __restrict__ out, int col0)
{
    int bp = blockIdx.x;
    int p = bp & 7, b = bp >> 3;
    const float* hp = g_heatp + (size_t)bp * HEADS_ * S_;
    int tid = threadIdx.x;

    float best = -FLT_MAX;
    int bidx = 0;
    for (int s = tid; s < S_; s += 256) {
        float v = 0.f;
        #pragma unroll
        for (int h = 0; h < HEADS_; h++) v += hp[(size_t)h * S_ + s];
        if (v > best) { best = v; bidx = s; }
    }
    __shared__ float sv[256];
    __shared__ int si[256];
    sv[tid] = best; si[tid] = bidx;
    __syncthreads();
    for (int off = 128; off > 0; off >>= 1) {
        if (tid < off) {
            bool take = (sv[tid + off] > sv[tid]) ||
                        (sv[tid + off] == sv[tid] && si[tid + off] < si[tid]);
            if (take) { sv[tid] = sv[tid + off]; si[tid] = si[tid + off]; }
        }
        __syncthreads();
    }
    if (tid == 0) out[384 + b * 24 + col0 + p] = (float)si[0];
}

// ---------------------------------------------------------------------------
extern "C" void kernel_launch(void* const* d_in, const int* in_sizes, int n_in,
                              void* d_out, int out_size)
{
    const float* x      = (const float*)d_in[0];
    const float* protos = (const float*)d_in[1];
    const float* Wq     = (const float*)d_in[2];
    const float* Wk     = (const float*)d_in[3];
    const float* Wv     = (const float*)d_in[4];
    float* out = (float*)d_out;

    constexpr int PROJ_SMEM   = (32 * 256 + 32 * 136) * 4;            // 50176
    constexpr int SCORES_SMEM = (32 * 256 + 32 * 136) * 4;            // 50176
    constexpr int OUT_SMEM    = (32 * 260 + 32 * 136 + 256) * 4;      // 51712

    cudaFuncSetAttribute(projKV_kernel<0>,
                         cudaFuncAttributeMaxDynamicSharedMemorySize, PROJ_SMEM);
    cudaFuncSetAttribute(projKV_kernel<1>,
                         cudaFuncAttributeMaxDynamicSharedMemorySize, PROJ_SMEM);
    cudaFuncSetAttribute(scores_kernel,
                         cudaFuncAttributeMaxDynamicSharedMemorySize, SCORES_SMEM);
    cudaFuncSetAttribute(out_slice_kernel,
                         cudaFuncAttributeMaxDynamicSharedMemorySize, OUT_SMEM);

    for (int i = 0; i < 3; i++) {
        const float* wq = Wq + (size_t)i * C_ * INNER_;
        const float* wk = Wk + (size_t)i * C_ * INNER_;
        const float* wv = Wv + (size_t)i * C_ * INNER_;

        projKV_kernel<0><<<dim3(S_ / 256, INNER_ / 64, B_), 256, PROJ_SMEM>>>(x, wk);
        projKV_kernel<1><<<dim3(S_ / 256, INNER_ / 64, B_), 256, PROJ_SMEM>>>(x, wv);
        projQ_kernel<<<dim3(1, INNER_ / 64, SPLITS_), 256>>>(
            protos + (size_t)i * SPLITS_ * C_ * L_, wq);

        scores_kernel<<<dim3(4, B_ * HEADS_ * SPLITS_), 256, SCORES_SMEM>>>();
        invz_kernel<<<256, 256>>>();
        out_slice_kernel<<<dim3(2, 4, 128), 256, OUT_SMEM>>>();
        finish_kernel<<<B_ * HEADS_ * SPLITS_, 256>>>();
        reduce_dist_kernel<<<1, 128>>>(out, i * SPLITS_);
        argmax_kernel<<<B_ * SPLITS_, 256>>>(out, i * SPLITS_);
    }
}

// round 7
// speedup vs baseline: 1.1484x; 1.1484x over previous
#include <cuda_runtime.h>
#include <math.h>
#include <float.h>

// ---------------------------------------------------------------------------
// MultiLatentSpaceSimilarity — fp32 f32x2 (R5 inner loops) + transposed E
// (g_E[bhp][s][l]) so the out kernel ingests without smem scatter.
// B=16, C=256, S=1024, 3 groups x 8 splits, L=64, HEADS=8, DH=64, INNER=512
// ---------------------------------------------------------------------------

constexpr int B_ = 16, C_ = 256, S_ = 1024;
constexpr int SPLITS_ = 8, L_ = 64, HEADS_ = 8, DH_ = 64, INNER_ = 512;
constexpr float SCALE_ = 0.125f;

// Static device scratch
__device__ float g_K[(size_t)B_ * INNER_ * S_];   // [b][h*64+d][s]
__device__ float g_V[(size_t)B_ * INNER_ * S_];   // [b][h*64+d][s]
__device__ float g_Q[SPLITS_ * L_ * INNER_];      // [p][l][n]
__device__ float g_E[(size_t)B_ * HEADS_ * SPLITS_ * S_ * L_]; // [bhp][s][l]
__device__ float g_Zp[B_ * HEADS_ * SPLITS_ * 4 * L_];         // partial Z
__device__ float g_invZ[B_ * HEADS_ * SPLITS_ * L_];           // 1/Z
__device__ float g_outp[(size_t)4 * 128 * 2 * 64 * 256];       // [sz][bh][rowG][d][row]
__device__ float g_heatp[(size_t)B_ * SPLITS_ * HEADS_ * S_];  // [(b*8+p)*8+h][s]
__device__ float g_distp[B_ * HEADS_ * SPLITS_];

typedef unsigned long long ull;

__device__ __forceinline__ void ffma2(ull& d, ull a, ull b)
{
    asm("fma.rn.f32x2 %0, %1, %2, %0;" : "+l"(d) : "l"(a), "l"(b));
}
__device__ __forceinline__ float2 unpk(ull v)
{
    float2 r;
    asm("mov.b64 {%0, %1}, %2;" : "=f"(r.x), "=f"(r.y) : "l"(v));
    return r;
}
__device__ __forceinline__ ull pack2f(float a, float b)
{
    ull r;
    asm("mov.b64 %0, {%1, %2};" : "=l"(r) : "f"(a), "f"(b));
    return r;
}
__device__ __forceinline__ ull pack2(float v)
{
    ull r;
    asm("mov.b64 %0, {%1, %1};" : "=l"(r) : "f"(v));
    return r;
}
// load 8 broadcast floats (warp-uniform) and pack to 8 {v,v} pairs
__device__ __forceinline__ void ld_bcast8(const float* p, ull* w)
{
    float4 b0 = *(const float4*)p;
    float4 b1 = *(const float4*)(p + 4);
    w[0] = pack2(b0.x); w[1] = pack2(b0.y); w[2] = pack2(b0.z); w[3] = pack2(b0.w);
    w[4] = pack2(b1.x); w[5] = pack2(b1.y); w[6] = pack2(b1.z); w[7] = pack2(b1.w);
}

// ---------------------------------------------------------------------------
// K/V projection: out[b][n][m] = sum_c A[b][c][m] * W[c][n]   (R5 verbatim)
// ---------------------------------------------------------------------------
template <int DST>
__global__ __launch_bounds__(256, 2) void projKV_kernel(
    const float* __restrict__ A, const float* __restrict__ W)
{
    extern __shared__ float sm[];
    float* As = sm;                 // [32][256]
    float* Ws = sm + 32 * 256;      // [32][68]

    float* outp = (DST == 0) ? g_K : g_V;
    int tid = threadIdx.x;
    int tx = tid & 31, wy = tid >> 5;
    int m0 = blockIdx.x * 256, n0 = blockIdx.y * 64;
    int batch = blockIdx.z;
    const float* Ab = A + (size_t)batch * C_ * S_;

    ull acc[8][4] = {};
    for (int c0 = 0; c0 < C_; c0 += 32) {
        __syncthreads();
        #pragma unroll
        for (int it = 0; it < 8; it++) {
            int idx = tid + it * 256;
            int c = idx >> 6, mq = idx & 63;
            *(float4*)&As[c * 256 + mq * 4] =
                *(const float4*)&Ab[(size_t)(c0 + c) * S_ + m0 + mq * 4];
        }
        #pragma unroll
        for (int it = 0; it < 2; it++) {
            int idx = tid + it * 256;
            int c = idx >> 4, nq = idx & 15;
            *(float4*)&Ws[c * 68 + nq * 4] =
                *(const float4*)&W[(size_t)(c0 + c) * INNER_ + n0 + nq * 4];
        }
        __syncthreads();
        #pragma unroll 8
        for (int c = 0; c < 32; c++) {
            const float* ar = &As[c * 256 + tx * 8];
            ulonglong2 a01 = *(const ulonglong2*)ar;
            ulonglong2 a23 = *(const ulonglong2*)(ar + 4);
            ull ap[4] = {a01.x, a01.y, a23.x, a23.y};
            ull wp[8];
            ld_bcast8(&Ws[c * 68 + wy * 8], wp);
            #pragma unroll
            for (int ni = 0; ni < 8; ni++)
                #pragma unroll
                for (int mj = 0; mj < 4; mj++)
                    ffma2(acc[ni][mj], wp[ni], ap[mj]);
        }
    }

    #pragma unroll
    for (int ni = 0; ni < 8; ni++) {
        int n = n0 + wy * 8 + ni;
        float2 f0 = unpk(acc[ni][0]), f1 = unpk(acc[ni][1]);
        float2 f2 = unpk(acc[ni][2]), f3 = unpk(acc[ni][3]);
        float* orow = &outp[((size_t)batch * INNER_ + n) * S_ + m0 + tx * 8];
        *(float4*)&orow[0] = make_float4(f0.x, f0.y, f1.x, f1.y);
        *(float4*)&orow[4] = make_float4(f2.x, f2.y, f3.x, f3.y);
    }
}

// ---------------------------------------------------------------------------
// Q projection (small). out g_Q[p][l][n]   (R5 verbatim)
// ---------------------------------------------------------------------------
__global__ void projQ_kernel(const float* __restrict__ A,
                             const float* __restrict__ W)
{
    __shared__ __align__(16) float As[32][68];   // [c][l]
    __shared__ __align__(16) float Wd[32][132];  // [c][2n] dup
    int tid = threadIdx.x;
    int txq = tid & 15, tyq = tid >> 4;
    int n0 = blockIdx.y * 64;
    int p = blockIdx.z;
    const float* Ab = A + (size_t)p * C_ * L_;

    ull acc[4][2] = {};
    for (int c0 = 0; c0 < C_; c0 += 32) {
        __syncthreads();
        for (int idx = tid; idx < 512; idx += 256) {
            int c = idx >> 4, q = idx & 15;
            *(float4*)&As[c][q * 4] =
                *(const float4*)&Ab[(size_t)(c0 + c) * L_ + q * 4];
            float4 w = *(const float4*)&W[(size_t)(c0 + c) * INNER_ + n0 + q * 4];
            Wd[c][q * 8 + 0] = w.x; Wd[c][q * 8 + 1] = w.x;
            Wd[c][q * 8 + 2] = w.y; Wd[c][q * 8 + 3] = w.y;
            Wd[c][q * 8 + 4] = w.z; Wd[c][q * 8 + 5] = w.z;
            Wd[c][q * 8 + 6] = w.w; Wd[c][q * 8 + 7] = w.w;
        }
        __syncthreads();
        #pragma unroll
        for (int cc = 0; cc < 32; cc++) {
            ulonglong2 am  = *(ulonglong2*)&As[cc][txq * 4];
            ulonglong2 w01 = *(ulonglong2*)&Wd[cc][tyq * 8];
            ulonglong2 w23 = *(ulonglong2*)&Wd[cc][tyq * 8 + 4];
            ffma2(acc[0][0], w01.x, am.x); ffma2(acc[0][1], w01.x, am.y);
            ffma2(acc[1][0], w01.y, am.x); ffma2(acc[1][1], w01.y, am.y);
            ffma2(acc[2][0], w23.x, am.x); ffma2(acc[2][1], w23.x, am.y);
            ffma2(acc[3][0], w23.y, am.x); ffma2(acc[3][1], w23.y, am.y);
        }
    }
    #pragma unroll
    for (int i4 = 0; i4 < 4; i4++) {
        int n = n0 + tyq * 4 + i4;
        float2 a = unpk(acc[i4][0]), b2 = unpk(acc[i4][1]);
        int l = txq * 4;
        g_Q[((size_t)p * L_ + l + 0) * INNER_ + n] = a.x;
        g_Q[((size_t)p * L_ + l + 1) * INNER_ + n] = a.y;
        g_Q[((size_t)p * L_ + l + 2) * INNER_ + n] = b2.x;
        g_Q[((size_t)p * L_ + l + 3) * INNER_ + n] = b2.y;
    }
}

// ---------------------------------------------------------------------------
// Scores: E_T[bhp][s][l] = exp(SCALE*q.k); Zp partials. Grid (4 sq, 1024 bhp).
// tx -> s (8/lane), wy -> l (8/warp, broadcast). Q persistent [64][68].
// ---------------------------------------------------------------------------
__global__ __launch_bounds__(256, 2) void scores_kernel()
{
    extern __shared__ float sm[];
    float* Kt = sm;                 // [32][256]
    float* Qs = sm + 32 * 256;      // [64][68]  Qs[d][l]

    int sq = blockIdx.x;
    int bhp = blockIdx.y;
    int p = bhp & 7, h = (bhp >> 3) & 7, b = bhp >> 6;
    int s0 = sq * 256;
    int tid = threadIdx.x;
    int tx = tid & 31, wy = tid >> 5;

    const float* kbase = g_K + ((size_t)(b * HEADS_ + h) * DH_) * S_ + s0;
    const float* qbase = g_Q + (size_t)p * L_ * INNER_ + h * DH_;

    // Q once: 64 l x 64 d -> Qs[d][l]
    #pragma unroll
    for (int it = 0; it < 4; it++) {
        int idx = tid + it * 256;
        int dq = idx & 15, l = idx >> 4;
        float4 q = *(const float4*)&qbase[(size_t)l * INNER_ + dq * 4];
        Qs[(dq * 4 + 0) * 68 + l] = q.x;
        Qs[(dq * 4 + 1) * 68 + l] = q.y;
        Qs[(dq * 4 + 2) * 68 + l] = q.z;
        Qs[(dq * 4 + 3) * 68 + l] = q.w;
    }

    ull acc[8][4] = {};                          // [l][s-pair]
    for (int d0 = 0; d0 < 64; d0 += 32) {
        __syncthreads();
        #pragma unroll
        for (int it = 0; it < 8; it++) {
            int idx = tid + it * 256;
            int d = idx >> 6, sqq = idx & 63;
            *(float4*)&Kt[d * 256 + sqq * 4] =
                *(const float4*)&kbase[(size_t)(d0 + d) * S_ + sqq * 4];
        }
        __syncthreads();
        #pragma unroll 8
        for (int d = 0; d < 32; d++) {
            const float* kr = &Kt[d * 256 + tx * 8];
            ulonglong2 k01 = *(const ulonglong2*)kr;
            ulonglong2 k23 = *(const ulonglong2*)(kr + 4);
            ull kp[4] = {k01.x, k01.y, k23.x, k23.y};
            ull qp[8];
            ld_bcast8(&Qs[(d0 + d) * 68 + wy * 8], qp);
            #pragma unroll
            for (int li = 0; li < 8; li++)
                #pragma unroll
                for (int sj = 0; sj < 4; sj++)
                    ffma2(acc[li][sj], qp[li], kp[sj]);
        }
    }

    // exp in place (packed back into acc) + partial Z
    #pragma unroll
    for (int li = 0; li < 8; li++) {
        int l = wy * 8 + li;
        float zl = 0.f;
        #pragma unroll
        for (int sj = 0; sj < 4; sj++) {
            float2 f = unpk(acc[li][sj]);
            float e0 = __expf(f.x * SCALE_);
            float e1 = __expf(f.y * SCALE_);
            zl += e0 + e1;
            acc[li][sj] = pack2f(e0, e1);
        }
        #pragma unroll
        for (int off = 16; off; off >>= 1)
            zl += __shfl_xor_sync(0xffffffffu, zl, off);
        if (tx == 0) g_Zp[(bhp * 4 + sq) * 64 + l] = zl;
    }

    // transposed store: E_T[s][l], one 32B sector per lane per s
    float* ebase = g_E + ((size_t)bhp * S_ + s0 + tx * 8) * 64 + wy * 8;
    #pragma unroll
    for (int sjp = 0; sjp < 4; sjp++) {
        float2 t0 = unpk(acc[0][sjp]), t1 = unpk(acc[1][sjp]);
        float2 t2 = unpk(acc[2][sjp]), t3 = unpk(acc[3][sjp]);
        float2 t4 = unpk(acc[4][sjp]), t5 = unpk(acc[5][sjp]);
        float2 t6 = unpk(acc[6][sjp]), t7 = unpk(acc[7][sjp]);
        float* e0 = ebase + (size_t)(2 * sjp) * 64;
        *(float4*)&e0[0]      = make_float4(t0.x, t1.x, t2.x, t3.x);
        *(float4*)&e0[4]      = make_float4(t4.x, t5.x, t6.x, t7.x);
        *(float4*)&e0[64]     = make_float4(t0.y, t1.y, t2.y, t3.y);
        *(float4*)&e0[68]     = make_float4(t4.y, t5.y, t6.y, t7.y);
    }
}

// ---------------------------------------------------------------------------
// invZ[bhp*64+l] = 1 / sum_j Zp[(bhp*4+j)*64+l]
// ---------------------------------------------------------------------------
__global__ void invz_kernel()
{
    int i = blockIdx.x * 256 + threadIdx.x;
    int bhp = i >> 6, l = i & 63;
    float z = 0.f;
    #pragma unroll
    for (int j = 0; j < 4; j++) z += g_Zp[(bhp * 4 + j) * 64 + l];
    g_invZ[i] = 1.0f / z;
}

// ---------------------------------------------------------------------------
// Out slices: rows = 256 (4 p's x 64 l), d = 64, s-slice = 256.
// Grid (2 rowG, 4 sz, 128 bh). E loads now coalesced from E_T[bhp][s][l],
// direct float4 STS (no scatter). V path unchanged (R5).
// ---------------------------------------------------------------------------
__global__ __launch_bounds__(256, 2) void out_slice_kernel()
{
    extern __shared__ float sm[];
    float* Es    = sm;                       // [32][260]  Es[s][row]
    float* Vs    = sm + 32 * 260;            // [32][68]   Vs[s][d]
    float* invZs = sm + 32 * 260 + 32 * 68;  // [256] (4p x 64l)

    int rowG = blockIdx.x;
    int sz   = blockIdx.y;
    int bh   = blockIdx.z;
    int b = bh >> 3, h = bh & 7;
    int tid = threadIdx.x;
    int tx = tid & 31, wy = tid >> 5;

    {
        int p_loc = tid >> 6, l = tid & 63;
        int bhp = bh * 8 + rowG * 4 + p_loc;
        invZs[tid] = g_invZ[bhp * 64 + l];
    }

    const float* vbase = g_V + ((size_t)(b * HEADS_ + h) * DH_) * S_;
    size_t ebase = (size_t)(bh * 8 + rowG * 4) * S_ * 64;  // E_T base (p=0)

    ull acc[8][4] = {};                      // [d][row-pair]
    for (int c = 0; c < 8; c++) {
        int s0 = sz * 256 + c * 32;
        __syncthreads();
        // E tile: 32 s x 256 rows, direct float4 copy from E_T
        #pragma unroll
        for (int it = 0; it < 8; it++) {
            int idx = tid + it * 256;
            int f4 = idx & 63;               // p = f4>>4, l4 = f4&15
            int s  = idx >> 6;
            int p_loc = f4 >> 4, l4 = f4 & 15;
            float4 e = *(const float4*)&g_E[
                ebase + ((size_t)p_loc * S_ + s0 + s) * 64 + l4 * 4];
            *(float4*)&Es[s * 260 + p_loc * 64 + l4 * 4] = e;
        }
        // V tile: 64 d x 32 s, transposed into Vs[s][d] (R5 path)
        #pragma unroll
        for (int it = 0; it < 2; it++) {
            int idx = tid + it * 256;
            int sq4 = idx & 7, d = idx >> 3;
            float4 v = *(const float4*)&vbase[(size_t)d * S_ + s0 + sq4 * 4];
            Vs[(sq4 * 4 + 0) * 68 + d] = v.x;
            Vs[(sq4 * 4 + 1) * 68 + d] = v.y;
            Vs[(sq4 * 4 + 2) * 68 + d] = v.z;
            Vs[(sq4 * 4 + 3) * 68 + d] = v.w;
        }
        __syncthreads();

        #pragma unroll 8
        for (int s = 0; s < 32; s++) {
            const float* er = &Es[s * 260 + tx * 8];
            ulonglong2 e01 = *(const ulonglong2*)er;
            ulonglong2 e23 = *(const ulonglong2*)(er + 4);
            ull ep[4] = {e01.x, e01.y, e23.x, e23.y};
            ull vp[8];
            ld_bcast8(&Vs[s * 68 + wy * 8], vp);
            #pragma unroll
            for (int di = 0; di < 8; di++)
                #pragma unroll
                for (int rj = 0; rj < 4; rj++)
                    ffma2(acc[di][rj], vp[di], ep[rj]);
        }

        if (tid < 128) {
            int s_loc = tid & 31, p_loc = tid >> 5;
            float hacc = 0.f;
            #pragma unroll 16
            for (int l = 0; l < 64; l++)
                hacc += Es[s_loc * 260 + p_loc * 64 + l] * invZs[p_loc * 64 + l];
            int p = rowG * 4 + p_loc;
            g_heatp[((size_t)(b * SPLITS_ + p) * HEADS_ + h) * S_ + s0 + s_loc] = hacc;
        }
    }

    // transpose acc -> buf[d][row64] per row-quarter, write coalesced
    float* buf = Es;  // reuse ([64][68] = 4352 floats)
    float* outBase = g_outp +
        (((size_t)(sz * 128 + bh) * 2 + rowG) * 64) * 256;
    for (int q = 0; q < 4; q++) {
        __syncthreads();
        if ((tx >> 3) == q) {
            int rl0 = (tx & 7) * 8;
            #pragma unroll
            for (int di = 0; di < 8; di++) {
                int d = wy * 8 + di;
                #pragma unroll
                for (int rj = 0; rj < 4; rj++) {
                    float2 f = unpk(acc[di][rj]);
                    *(float2*)&buf[d * 68 + rl0 + 2 * rj] = f;
                }
            }
        }
        __syncthreads();
        #pragma unroll
        for (int it = 0; it < 4; it++) {
            int idx = tid + it * 256;
            int d = idx >> 4, r4 = idx & 15;
            float4 v = *(float4*)&buf[d * 68 + r4 * 4];
            *(float4*)&outBase[(size_t)d * 256 + q * 64 + r4 * 4] = v;
        }
    }
}

// ---------------------------------------------------------------------------
// Finish: per bhp, sum 4 slice partials, normalize, dist = sum (q-out)^2.
// ---------------------------------------------------------------------------
__global__ void finish_kernel()
{
    int bhp = blockIdx.x;
    int p = bhp & 7, h = (bhp >> 3) & 7, b = bhp >> 6;
    int bh = b * 8 + h;
    int rowG = p >> 2, p_loc = p & 3;
    int tid = threadIdx.x;

    const float* qb = g_Q + (size_t)p * L_ * INNER_ + h * DH_;
    float ssum = 0.f;
    #pragma unroll
    for (int it = 0; it < 16; it++) {
        int idx = tid + it * 256;
        int d = idx >> 6, l = idx & 63;
        float v = 0.f;
        #pragma unroll
        for (int sz = 0; sz < 4; sz++)
            v += g_outp[(((size_t)(sz * 128 + bh) * 2 + rowG) * 64 + d) * 256 +
                        p_loc * 64 + l];
        float o = v * g_invZ[bhp * 64 + l];
        float diff = qb[(size_t)l * INNER_ + d] - o;
        ssum += diff * diff;
    }
    __shared__ float red[256];
    red[tid] = ssum;
    __syncthreads();
    for (int off = 128; off > 0; off >>= 1) {
        if (tid < off) red[tid] += red[tid + off];
        __syncthreads();
    }
    if (tid == 0) g_distp[bhp] = red[0];
}

// ---------------------------------------------------------------------------
__global__ void reduce_dist_kernel(float* __restrict__ out, int col0)
{
    int t = threadIdx.x;
    if (t < B_ * SPLITS_) {
        int p = t & 7, b = t >> 3;
        float s = 0.f;
        #pragma unroll
        for (int h = 0; h < HEADS_; h++) s += g_distp[b * 64 + h * 8 + p];
        out[b * 24 + col0 + p] = s * (1.0f / (L_ * INNER_));
    }
}

__global__ void argmax_kernel(float* __restrict__ out, int col0)
{
    int bp = blockIdx.x;
    int p = bp & 7, b = bp >> 3;
    const float* hp = g_heatp + (size_t)bp * HEADS_ * S_;
    int tid = threadIdx.x;

    float best = -FLT_MAX;
    int bidx = 0;
    for (int s = tid; s < S_; s += 256) {
        float v = 0.f;
        #pragma unroll
        for (int h = 0; h < HEADS_; h++) v += hp[(size_t)h * S_ + s];
        if (v > best) { best = v; bidx = s; }
    }
    __shared__ float sv[256];
    __shared__ int si[256];
    sv[tid] = best; si[tid] = bidx;
    __syncthreads();
    for (int off = 128; off > 0; off >>= 1) {
        if (tid < off) {
            bool take = (sv[tid + off] > sv[tid]) ||
                        (sv[tid + off] == sv[tid] && si[tid + off] < si[tid]);
            if (take) { sv[tid] = sv[tid + off]; si[tid] = si[tid + off]; }
        }
        __syncthreads();
    }
    if (tid == 0) out[384 + b * 24 + col0 + p] = (float)si[0];
}

// ---------------------------------------------------------------------------
extern "C" void kernel_launch(void* const* d_in, const int* in_sizes, int n_in,
                              void* d_out, int out_size)
{
    const float* x      = (const float*)d_in[0];
    const float* protos = (const float*)d_in[1];
    const float* Wq     = (const float*)d_in[2];
    const float* Wk     = (const float*)d_in[3];
    const float* Wv     = (const float*)d_in[4];
    float* out = (float*)d_out;

    constexpr int PROJ_SMEM   = (32 * 256 + 32 * 68) * 4;            // 41472
    constexpr int SCORES_SMEM = (32 * 256 + 64 * 68) * 4;            // 50176
    constexpr int OUT_SMEM    = (32 * 260 + 32 * 68 + 256) * 4;      // 42992

    cudaFuncSetAttribute(projKV_kernel<0>,
                         cudaFuncAttributeMaxDynamicSharedMemorySize, PROJ_SMEM);
    cudaFuncSetAttribute(projKV_kernel<1>,
                         cudaFuncAttributeMaxDynamicSharedMemorySize, PROJ_SMEM);
    cudaFuncSetAttribute(scores_kernel,
                         cudaFuncAttributeMaxDynamicSharedMemorySize, SCORES_SMEM);
    cudaFuncSetAttribute(out_slice_kernel,
                         cudaFuncAttributeMaxDynamicSharedMemorySize, OUT_SMEM);

    for (int i = 0; i < 3; i++) {
        const float* wq = Wq + (size_t)i * C_ * INNER_;
        const float* wk = Wk + (size_t)i * C_ * INNER_;
        const float* wv = Wv + (size_t)i * C_ * INNER_;

        projKV_kernel<0><<<dim3(S_ / 256, INNER_ / 64, B_), 256, PROJ_SMEM>>>(x, wk);
        projKV_kernel<1><<<dim3(S_ / 256, INNER_ / 64, B_), 256, PROJ_SMEM>>>(x, wv);
        projQ_kernel<<<dim3(1, INNER_ / 64, SPLITS_), 256>>>(
            protos + (size_t)i * SPLITS_ * C_ * L_, wq);

        scores_kernel<<<dim3(4, B_ * HEADS_ * SPLITS_), 256, SCORES_SMEM>>>();
        invz_kernel<<<256, 256>>>();
        out_slice_kernel<<<dim3(2, 4, 128), 256, OUT_SMEM>>>();
        finish_kernel<<<B_ * HEADS_ * SPLITS_, 256>>>();
        reduce_dist_kernel<<<1, 128>>>(out, i * SPLITS_);
        argmax_kernel<<<B_ * SPLITS_, 256>>>(out, i * SPLITS_);
    }
}

// round 8
// speedup vs baseline: 1.3014x; 1.1333x over previous
#include <cuda_runtime.h>
#include <math.h>
#include <float.h>

// ---------------------------------------------------------------------------
// MultiLatentSpaceSimilarity — fp32 f32x2, 8x4 thread tiles, 3 CTAs/SM
// (24 warps: latency hiding), R5 memory layouts.
// B=16, C=256, S=1024, 3 groups x 8 splits, L=64, HEADS=8, DH=64, INNER=512
// ---------------------------------------------------------------------------

constexpr int B_ = 16, C_ = 256, S_ = 1024;
constexpr int SPLITS_ = 8, L_ = 64, HEADS_ = 8, DH_ = 64, INNER_ = 512;
constexpr float SCALE_ = 0.125f;

// Static device scratch
__device__ float g_K[(size_t)B_ * INNER_ * S_];   // [b][h*64+d][s]
__device__ float g_V[(size_t)B_ * INNER_ * S_];   // [b][h*64+d][s]
__device__ float g_Q[SPLITS_ * L_ * INNER_];      // [p][l][n]
__device__ float g_E[(size_t)B_ * HEADS_ * SPLITS_ * L_ * S_]; // [bhp][l][s]
__device__ float g_Zp[B_ * HEADS_ * SPLITS_ * 8 * L_];         // 8 partial Z
__device__ float g_invZ[B_ * HEADS_ * SPLITS_ * L_];           // 1/Z
__device__ float g_outp[(size_t)4 * 128 * 4 * 64 * 128];       // [sz][bh][rowG][d][row]
__device__ float g_heatp[(size_t)B_ * SPLITS_ * HEADS_ * S_];  // [(b*8+p)*8+h][s]
__device__ float g_distp[B_ * HEADS_ * SPLITS_];

typedef unsigned long long ull;

__device__ __forceinline__ void ffma2(ull& d, ull a, ull b)
{
    asm("fma.rn.f32x2 %0, %1, %2, %0;" : "+l"(d) : "l"(a), "l"(b));
}
__device__ __forceinline__ float2 unpk(ull v)
{
    float2 r;
    asm("mov.b64 {%0, %1}, %2;" : "=f"(r.x), "=f"(r.y) : "l"(v));
    return r;
}
__device__ __forceinline__ ull pack2(float v)
{
    ull r;
    asm("mov.b64 %0, {%1, %1};" : "=l"(r) : "f"(v));
    return r;
}
// load 4 broadcast floats (warp-uniform LDS.128) -> 4 {v,v} pairs
__device__ __forceinline__ void ld_bcast4(const float* p, ull* w)
{
    float4 b = *(const float4*)p;
    w[0] = pack2(b.x); w[1] = pack2(b.y); w[2] = pack2(b.z); w[3] = pack2(b.w);
}

// ---------------------------------------------------------------------------
// K/V projection: out[b][n][m] = sum_c A[b][c][m] * W[c][n]
// CTA tile 128(m) x 64(n); tx -> 4 m, wy -> 8 n (broadcast). 3 CTAs/SM.
// ---------------------------------------------------------------------------
template <int DST>
__global__ __launch_bounds__(256, 3) void projKV_kernel(
    const float* __restrict__ A, const float* __restrict__ W)
{
    extern __shared__ float sm[];
    float* As = sm;                 // [32][128]
    float* Ws = sm + 32 * 128;      // [32][68]

    float* outp = (DST == 0) ? g_K : g_V;
    int tid = threadIdx.x;
    int tx = tid & 31, wy = tid >> 5;
    int m0 = blockIdx.x * 128, n0 = blockIdx.y * 64;
    int batch = blockIdx.z;
    const float* Ab = A + (size_t)batch * C_ * S_;

    ull acc[8][2] = {};                          // [n][m-pair]
    for (int c0 = 0; c0 < C_; c0 += 32) {
        __syncthreads();
        #pragma unroll
        for (int it = 0; it < 4; it++) {
            int idx = tid + it * 256;
            int c = idx >> 5, mq = idx & 31;
            *(float4*)&As[c * 128 + mq * 4] =
                *(const float4*)&Ab[(size_t)(c0 + c) * S_ + m0 + mq * 4];
        }
        #pragma unroll
        for (int it = 0; it < 2; it++) {
            int idx = tid + it * 256;
            int c = idx >> 4, nq = idx & 15;
            *(float4*)&Ws[c * 68 + nq * 4] =
                *(const float4*)&W[(size_t)(c0 + c) * INNER_ + n0 + nq * 4];
        }
        __syncthreads();
        #pragma unroll 4
        for (int c = 0; c < 32; c++) {
            ulonglong2 av = *(const ulonglong2*)&As[c * 128 + tx * 4];
            ull wp[4];
            ld_bcast4(&Ws[c * 68 + wy * 8], wp);
            #pragma unroll
            for (int ni = 0; ni < 4; ni++) {
                ffma2(acc[ni][0], wp[ni], av.x);
                ffma2(acc[ni][1], wp[ni], av.y);
            }
            ld_bcast4(&Ws[c * 68 + wy * 8 + 4], wp);
            #pragma unroll
            for (int ni = 0; ni < 4; ni++) {
                ffma2(acc[4 + ni][0], wp[ni], av.x);
                ffma2(acc[4 + ni][1], wp[ni], av.y);
            }
        }
    }

    #pragma unroll
    for (int ni = 0; ni < 8; ni++) {
        int n = n0 + wy * 8 + ni;
        float2 f0 = unpk(acc[ni][0]), f1 = unpk(acc[ni][1]);
        *(float4*)&outp[((size_t)batch * INNER_ + n) * S_ + m0 + tx * 4] =
            make_float4(f0.x, f0.y, f1.x, f1.y);
    }
}

// ---------------------------------------------------------------------------
// Q projection (small; unchanged from R5). out g_Q[p][l][n]
// ---------------------------------------------------------------------------
__global__ void projQ_kernel(const float* __restrict__ A,
                             const float* __restrict__ W)
{
    __shared__ __align__(16) float As[32][68];   // [c][l]
    __shared__ __align__(16) float Wd[32][132];  // [c][2n] dup
    int tid = threadIdx.x;
    int txq = tid & 15, tyq = tid >> 4;
    int n0 = blockIdx.y * 64;
    int p = blockIdx.z;
    const float* Ab = A + (size_t)p * C_ * L_;

    ull acc[4][2] = {};
    for (int c0 = 0; c0 < C_; c0 += 32) {
        __syncthreads();
        for (int idx = tid; idx < 512; idx += 256) {
            int c = idx >> 4, q = idx & 15;
            *(float4*)&As[c][q * 4] =
                *(const float4*)&Ab[(size_t)(c0 + c) * L_ + q * 4];
            float4 w = *(const float4*)&W[(size_t)(c0 + c) * INNER_ + n0 + q * 4];
            Wd[c][q * 8 + 0] = w.x; Wd[c][q * 8 + 1] = w.x;
            Wd[c][q * 8 + 2] = w.y; Wd[c][q * 8 + 3] = w.y;
            Wd[c][q * 8 + 4] = w.z; Wd[c][q * 8 + 5] = w.z;
            Wd[c][q * 8 + 6] = w.w; Wd[c][q * 8 + 7] = w.w;
        }
        __syncthreads();
        #pragma unroll
        for (int cc = 0; cc < 32; cc++) {
            ulonglong2 am  = *(ulonglong2*)&As[cc][txq * 4];
            ulonglong2 w01 = *(ulonglong2*)&Wd[cc][tyq * 8];
            ulonglong2 w23 = *(ulonglong2*)&Wd[cc][tyq * 8 + 4];
            ffma2(acc[0][0], w01.x, am.x); ffma2(acc[0][1], w01.x, am.y);
            ffma2(acc[1][0], w01.y, am.x); ffma2(acc[1][1], w01.y, am.y);
            ffma2(acc[2][0], w23.x, am.x); ffma2(acc[2][1], w23.x, am.y);
            ffma2(acc[3][0], w23.y, am.x); ffma2(acc[3][1], w23.y, am.y);
        }
    }
    #pragma unroll
    for (int i4 = 0; i4 < 4; i4++) {
        int n = n0 + tyq * 4 + i4;
        float2 a = unpk(acc[i4][0]), b2 = unpk(acc[i4][1]);
        int l = txq * 4;
        g_Q[((size_t)p * L_ + l + 0) * INNER_ + n] = a.x;
        g_Q[((size_t)p * L_ + l + 1) * INNER_ + n] = a.y;
        g_Q[((size_t)p * L_ + l + 2) * INNER_ + n] = b2.x;
        g_Q[((size_t)p * L_ + l + 3) * INNER_ + n] = b2.y;
    }
}

// ---------------------------------------------------------------------------
// Scores: E[bhp][l][s] = exp(SCALE*q.k); Zp partials (8 per bhp).
// Grid (8 sq, 1024 bhp). tx -> 4 s, wy -> 8 l (broadcast). d tiled 2x32.
// ---------------------------------------------------------------------------
__global__ __launch_bounds__(256, 3) void scores_kernel()
{
    extern __shared__ float sm[];
    float* Kt = sm;                 // [32][128]
    float* Qs = sm + 32 * 128;      // [32][68]  Qs[d][l]

    int sq = blockIdx.x;
    int bhp = blockIdx.y;
    int p = bhp & 7, h = (bhp >> 3) & 7, b = bhp >> 6;
    int s0 = sq * 128;
    int tid = threadIdx.x;
    int tx = tid & 31, wy = tid >> 5;

    const float* kbase = g_K + ((size_t)(b * HEADS_ + h) * DH_) * S_ + s0;
    const float* qbase = g_Q + (size_t)p * L_ * INNER_ + h * DH_;

    ull acc[8][2] = {};                          // [l][s-pair]
    for (int d0 = 0; d0 < 64; d0 += 32) {
        __syncthreads();
        #pragma unroll
        for (int it = 0; it < 4; it++) {
            int idx = tid + it * 256;
            int d = idx >> 5, sqq = idx & 31;
            *(float4*)&Kt[d * 128 + sqq * 4] =
                *(const float4*)&kbase[(size_t)(d0 + d) * S_ + sqq * 4];
        }
        #pragma unroll
        for (int it = 0; it < 2; it++) {
            int idx = tid + it * 256;
            int dq = idx & 7, l = idx >> 3;
            float4 q = *(const float4*)&qbase[(size_t)l * INNER_ + d0 + dq * 4];
            Qs[(dq * 4 + 0) * 68 + l] = q.x;
            Qs[(dq * 4 + 1) * 68 + l] = q.y;
            Qs[(dq * 4 + 2) * 68 + l] = q.z;
            Qs[(dq * 4 + 3) * 68 + l] = q.w;
        }
        __syncthreads();
        #pragma unroll 4
        for (int d = 0; d < 32; d++) {
            ulonglong2 kv = *(const ulonglong2*)&Kt[d * 128 + tx * 4];
            ull qp[4];
            ld_bcast4(&Qs[d * 68 + wy * 8], qp);
            #pragma unroll
            for (int li = 0; li < 4; li++) {
                ffma2(acc[li][0], qp[li], kv.x);
                ffma2(acc[li][1], qp[li], kv.y);
            }
            ld_bcast4(&Qs[d * 68 + wy * 8 + 4], qp);
            #pragma unroll
            for (int li = 0; li < 4; li++) {
                ffma2(acc[4 + li][0], qp[li], kv.x);
                ffma2(acc[4 + li][1], qp[li], kv.y);
            }
        }
    }

    float* erow = g_E + (size_t)bhp * L_ * S_ + s0;
    #pragma unroll
    for (int li = 0; li < 8; li++) {
        int l = wy * 8 + li;
        float2 a0 = unpk(acc[li][0]), a1 = unpk(acc[li][1]);
        float e0 = __expf(a0.x * SCALE_), e1 = __expf(a0.y * SCALE_);
        float e2 = __expf(a1.x * SCALE_), e3 = __expf(a1.y * SCALE_);
        *(float4*)&erow[(size_t)l * S_ + tx * 4] = make_float4(e0, e1, e2, e3);
        float z = (e0 + e1) + (e2 + e3);
        #pragma unroll
        for (int off = 16; off; off >>= 1)
            z += __shfl_xor_sync(0xffffffffu, z, off);
        if (tx == 0) g_Zp[(bhp * 8 + sq) * 64 + l] = z;
    }
}

// ---------------------------------------------------------------------------
// invZ[bhp*64+l] = 1 / sum_j Zp[(bhp*8+j)*64+l]
// ---------------------------------------------------------------------------
__global__ void invz_kernel()
{
    int i = blockIdx.x * 256 + threadIdx.x;
    int bhp = i >> 6, l = i & 63;
    float z = 0.f;
    #pragma unroll
    for (int j = 0; j < 8; j++) z += g_Zp[(bhp * 8 + j) * 64 + l];
    g_invZ[i] = 1.0f / z;
}

// ---------------------------------------------------------------------------
// Out slices: rows = 128 (2 p's x 64 l, shared V), d = 64, s-slice = 256.
// Grid (4 rowG, 4 sz, 128 bh). tx -> 4 rows, wy -> 8 d (broadcast V).
// ---------------------------------------------------------------------------
__global__ __launch_bounds__(256, 3) void out_slice_kernel()
{
    extern __shared__ float sm[];
    float* Es    = sm;                       // [32][132]  Es[s][row]
    float* Vs    = sm + 32 * 132;            // [32][68]   Vs[s][d]
    float* invZs = sm + 32 * 132 + 32 * 68;  // [128] (2p x 64l)

    int rowG = blockIdx.x;                   // 0..3 (p pairs)
    int sz   = blockIdx.y;                   // 0..3
    int bh   = blockIdx.z;                   // b*8+h
    int b = bh >> 3, h = bh & 7;
    int tid = threadIdx.x;
    int tx = tid & 31, wy = tid >> 5;

    if (tid < 128)
        invZs[tid] = g_invZ[(bh * 8 + rowG * 2) * 64 + tid];

    const float* vbase = g_V + ((size_t)(b * HEADS_ + h) * DH_) * S_;
    size_t ebase = (size_t)(bh * 8 + rowG * 2) * L_ * S_;  // rows contiguous

    ull acc[8][2] = {};                      // [d][row-pair]
    for (int c = 0; c < 8; c++) {
        int s0 = sz * 256 + c * 32;
        __syncthreads();
        // E tile: 128 rows x 32 s -> Es[s][row] (smem scatter, R5-style)
        #pragma unroll
        for (int it = 0; it < 4; it++) {
            int idx = tid + it * 256;
            int sq4 = idx & 7, r = idx >> 3;
            float4 e = *(const float4*)&g_E[ebase + (size_t)r * S_ + s0 + sq4 * 4];
            Es[(sq4 * 4 + 0) * 132 + r] = e.x;
            Es[(sq4 * 4 + 1) * 132 + r] = e.y;
            Es[(sq4 * 4 + 2) * 132 + r] = e.z;
            Es[(sq4 * 4 + 3) * 132 + r] = e.w;
        }
        // V tile: 64 d x 32 s -> Vs[s][d]
        #pragma unroll
        for (int it = 0; it < 2; it++) {
            int idx = tid + it * 256;
            int sq4 = idx & 7, d = idx >> 3;
            float4 v = *(const float4*)&vbase[(size_t)d * S_ + s0 + sq4 * 4];
            Vs[(sq4 * 4 + 0) * 68 + d] = v.x;
            Vs[(sq4 * 4 + 1) * 68 + d] = v.y;
            Vs[(sq4 * 4 + 2) * 68 + d] = v.z;
            Vs[(sq4 * 4 + 3) * 68 + d] = v.w;
        }
        __syncthreads();

        #pragma unroll 4
        for (int s = 0; s < 32; s++) {
            ulonglong2 ev = *(const ulonglong2*)&Es[s * 132 + tx * 4];
            ull vp[4];
            ld_bcast4(&Vs[s * 68 + wy * 8], vp);
            #pragma unroll
            for (int di = 0; di < 4; di++) {
                ffma2(acc[di][0], vp[di], ev.x);
                ffma2(acc[di][1], vp[di], ev.y);
            }
            ld_bcast4(&Vs[s * 68 + wy * 8 + 4], vp);
            #pragma unroll
            for (int di = 0; di < 4; di++) {
                ffma2(acc[4 + di][0], vp[di], ev.x);
                ffma2(acc[4 + di][1], vp[di], ev.y);
            }
        }

        // heat: threads 0..63 -> (s_loc 32, p_loc 2)
        if (tid < 64) {
            int s_loc = tid & 31, p_loc = tid >> 5;
            float hacc = 0.f;
            #pragma unroll 16
            for (int l = 0; l < 64; l++)
                hacc += Es[s_loc * 132 + p_loc * 64 + l] * invZs[p_loc * 64 + l];
            int p = rowG * 2 + p_loc;
            g_heatp[((size_t)(b * SPLITS_ + p) * HEADS_ + h) * S_ + s0 + s_loc] = hacc;
        }
    }

    // direct coalesced partial store: [sz][bh][rowG][d][row]
    float* outBase = g_outp +
        (((size_t)(sz * 128 + bh) * 4 + rowG) * 64) * 128;
    #pragma unroll
    for (int di = 0; di < 8; di++) {
        int d = wy * 8 + di;
        float2 f0 = unpk(acc[di][0]), f1 = unpk(acc[di][1]);
        *(float4*)&outBase[(size_t)d * 128 + tx * 4] =
            make_float4(f0.x, f0.y, f1.x, f1.y);
    }
}

// ---------------------------------------------------------------------------
// Finish: per bhp, sum 4 slice partials, normalize, dist = sum (q-out)^2.
// ---------------------------------------------------------------------------
__global__ void finish_kernel()
{
    int bhp = blockIdx.x;
    int p = bhp & 7, h = (bhp >> 3) & 7, b = bhp >> 6;
    int bh = b * 8 + h;
    int rowG = p >> 1, p_loc = p & 1;
    int tid = threadIdx.x;

    const float* qb = g_Q + (size_t)p * L_ * INNER_ + h * DH_;
    float ssum = 0.f;
    #pragma unroll
    for (int it = 0; it < 16; it++) {
        int idx = tid + it * 256;
        int d = idx >> 6, l = idx & 63;
        float v = 0.f;
        #pragma unroll
        for (int sz = 0; sz < 4; sz++)
            v += g_outp[(((size_t)(sz * 128 + bh) * 4 + rowG) * 64 + d) * 128 +
                        p_loc * 64 + l];
        float o = v * g_invZ[bhp * 64 + l];
        float diff = qb[(size_t)l * INNER_ + d] - o;
        ssum += diff * diff;
    }
    __shared__ float red[256];
    red[tid] = ssum;
    __syncthreads();
    for (int off = 128; off > 0; off >>= 1) {
        if (tid < off) red[tid] += red[tid + off];
        __syncthreads();
    }
    if (tid == 0) g_distp[bhp] = red[0];
}

// ---------------------------------------------------------------------------
__global__ void reduce_dist_kernel(float* __restrict__ out, int col0)
{
    int t = threadIdx.x;
    if (t < B_ * SPLITS_) {
        int p = t & 7, b = t >> 3;
        float s = 0.f;
        #pragma unroll
        for (int h = 0; h < HEADS_; h++) s += g_distp[b * 64 + h * 8 + p];
        out[b * 24 + col0 + p] = s * (1.0f / (L_ * INNER_));
    }
}

__global__ void argmax_kernel(float* __restrict__ out, int col0)
{
    int bp = blockIdx.x;
    int p = bp & 7, b = bp >> 3;
    const float* hp = g_heatp + (size_t)bp * HEADS_ * S_;
    int tid = threadIdx.x;

    float best = -FLT_MAX;
    int bidx = 0;
    for (int s = tid; s < S_; s += 256) {
        float v = 0.f;
        #pragma unroll
        for (int h = 0; h < HEADS_; h++) v += hp[(size_t)h * S_ + s];
        if (v > best) { best = v; bidx = s; }
    }
    __shared__ float sv[256];
    __shared__ int si[256];
    sv[tid] = best; si[tid] = bidx;
    __syncthreads();
    for (int off = 128; off > 0; off >>= 1) {
        if (tid < off) {
            bool take = (sv[tid + off] > sv[tid]) ||
                        (sv[tid + off] == sv[tid] && si[tid + off] < si[tid]);
            if (take) { sv[tid] = sv[tid + off]; si[tid] = si[tid + off]; }
        }
        __syncthreads();
    }
    if (tid == 0) out[384 + b * 24 + col0 + p] = (float)si[0];
}

// ---------------------------------------------------------------------------
extern "C" void kernel_launch(void* const* d_in, const int* in_sizes, int n_in,
                              void* d_out, int out_size)
{
    const float* x      = (const float*)d_in[0];
    const float* protos = (const float*)d_in[1];
    const float* Wq     = (const float*)d_in[2];
    const float* Wk     = (const float*)d_in[3];
    const float* Wv     = (const float*)d_in[4];
    float* out = (float*)d_out;

    constexpr int PROJ_SMEM   = (32 * 128 + 32 * 68) * 4;            // 25088
    constexpr int SCORES_SMEM = (32 * 128 + 32 * 68) * 4;            // 25088
    constexpr int OUT_SMEM    = (32 * 132 + 32 * 68 + 128) * 4;      // 26112

    for (int i = 0; i < 3; i++) {
        const float* wq = Wq + (size_t)i * C_ * INNER_;
        const float* wk = Wk + (size_t)i * C_ * INNER_;
        const float* wv = Wv + (size_t)i * C_ * INNER_;

        projKV_kernel<0><<<dim3(S_ / 128, INNER_ / 64, B_), 256, PROJ_SMEM>>>(x, wk);
        projKV_kernel<1><<<dim3(S_ / 128, INNER_ / 64, B_), 256, PROJ_SMEM>>>(x, wv);
        projQ_kernel<<<dim3(1, INNER_ / 64, SPLITS_), 256>>>(
            protos + (size_t)i * SPLITS_ * C_ * L_, wq);

        scores_kernel<<<dim3(8, B_ * HEADS_ * SPLITS_), 256, SCORES_SMEM>>>();
        invz_kernel<<<256, 256>>>();
        out_slice_kernel<<<dim3(4, 4, 128), 256, OUT_SMEM>>>();
        finish_kernel<<<B_ * HEADS_ * SPLITS_, 256>>>();
        reduce_dist_kernel<<<1, 128>>>(out, i * SPLITS_);
        argmax_kernel<<<B_ * SPLITS_, 256>>>(out, i * SPLITS_);
    }
}